// round 1
// baseline (speedup 1.0000x reference)
#include <cuda_runtime.h>

#define NB    4096
#define NBINS 64
#define NW    8              // warps per block (256 threads)
#define TPB   256

// Global scratch histogram (allocation-free: __device__ global)
__device__ int g_hist[NBINS];

__global__ void zero_hist_kernel() {
    if (threadIdx.x < NBINS) g_hist[threadIdx.x] = 0;
}

extern __shared__ float4 s_pts[];   // 4096 * 16B = 64 KB dynamic smem

__global__ __launch_bounds__(TPB, 3)
void hist_kernel(const float* __restrict__ x, int n) {
    __shared__ int s_h[NW][NBINS + 1];   // +1 pad: cross-warp bank-conflict-free

    const int tid  = threadIdx.x;
    const int w    = tid >> 5;
    const int lane = tid & 31;

    // Stage all points into shared memory as float4 (one LDS.128 per point later)
    for (int p = tid; p < n; p += TPB) {
        float a = x[3 * p + 0];
        float b = x[3 * p + 1];
        float c = x[3 * p + 2];
        s_pts[p] = make_float4(a, b, c, 0.0f);
    }
    for (int t = tid; t < NW * (NBINS + 1); t += TPB)
        (&s_h[0][0])[t] = 0;
    __syncthreads();

    // Block b handles rows (b, n-1-b): 4095-b + b = 4095 pairs -> perfect balance
    int rows[2];
    rows[0] = (int)blockIdx.x;
    rows[1] = n - 1 - (int)blockIdx.x;

    #pragma unroll
    for (int rr = 0; rr < 2; rr++) {
        const int i = rows[rr];
        const float4 pi = s_pts[i];
        // Uniform trip count across the warp; invalid lanes get t = -1
        for (int base = i + 1; base < n; base += TPB) {
            const int j = base + tid;
            int t = -1;
            if (j < n) {
                const float4 pj = s_pts[j];
                const float dx = pi.x - pj.x;
                const float dy = pi.y - pj.y;
                const float dz = pi.z - pj.z;
                // match jnp: squares + sequential adds, NO fma contraction
                const float s = __fadd_rn(__fadd_rn(__fmul_rn(dx, dx),
                                                    __fmul_rn(dy, dy)),
                                          __fmul_rn(dz, dz));
                const float d = __fsqrt_rn(s);          // IEEE sqrt, matches jnp.sqrt
                if (d <= 2.0f) {                        // t_max edge filter
                    int b = (int)ceilf(__fmul_rn(d, 31.5f));  // (STEPS-1)/(t_max-t_min)
                    b = b < 0 ? 0 : (b > NBINS - 1 ? NBINS - 1 : b);
                    t = b;
                }
            }
            // Warp-aggregate identical bins: one shared atomic per distinct bin
            const unsigned m = __match_any_sync(0xffffffffu, t);
            if (t >= 0 && (int)(__ffs(m) - 1) == lane)
                atomicAdd(&s_h[w][t], (int)__popc(m));
        }
    }
    __syncthreads();

    // Reduce per-warp copies, one global atomic per bin per block
    for (int t = tid; t < NBINS; t += TPB) {
        int s = 0;
        #pragma unroll
        for (int ww = 0; ww < NW; ww++) s += s_h[ww][t];
        if (s) atomicAdd(&g_hist[t], s);
    }
}

__global__ void finalize_kernel(float* __restrict__ out, int n) {
    // 64 bins: trivial sequential inclusive scan (exact: integer values < 2^24)
    if (threadIdx.x == 0) {
        float acc = 0.0f;
        for (int k = 0; k < NBINS; k++) {
            float v = -(float)g_hist[k];
            if (k == 0) v += (float)n;   // all vertices at filtration 0 -> bin 0
            acc += v;
            out[k] = acc;
        }
    }
}

extern "C" void kernel_launch(void* const* d_in, const int* in_sizes, int n_in,
                              void* d_out, int out_size) {
    const float* x = (const float*)d_in[0];
    float* out = (float*)d_out;
    const int n = in_sizes[0] / 3;     // 4096

    // Opt in to 64 KB dynamic shared memory (host-side attribute, capture-safe)
    cudaFuncSetAttribute(hist_kernel,
                         cudaFuncAttributeMaxDynamicSharedMemorySize,
                         NB * (int)sizeof(float4));

    zero_hist_kernel<<<1, 64>>>();
    hist_kernel<<<n / 2, TPB, NB * sizeof(float4)>>>(x, n);
    finalize_kernel<<<1, 32>>>(out, n);
}

// round 2
// speedup vs baseline: 1.6185x; 1.6185x over previous
#include <cuda_runtime.h>

#define TPB    256
#define NBINS  64          // output bins
#define SBINS  56          // reachable bins: ceil(31.5*sqrt(3)) = 55 max
#define GRID   444         // 148 SMs * 3 blocks/SM
#define NUNITS 2048        // row-pairs (i, n-1-i): each exactly 4095 pairs

// Global scratch histogram (allocation-free __device__ global).
// Invariant: zero at entry of every kernel_launch; finalize_kernel resets it.
__device__ int g_hist[NBINS];

extern __shared__ unsigned s_h[];   // [SBINS][TPB] u32, bank-conflict-free RMW

__global__ __launch_bounds__(TPB, 3)
void hist_kernel(const float* __restrict__ x, int n) {
    const int tid = threadIdx.x;

    // Zero private histograms (56 stores/thread)
    #pragma unroll
    for (int k = tid; k < SBINS * TPB; k += TPB) s_h[k] = 0u;
    __syncthreads();

    // Units are row-pairs (u, n-1-u): perfectly uniform 4095 pairs each.
    for (int u = blockIdx.x; u < NUNITS; u += GRID) {
        int rows[2];
        rows[0] = u;
        rows[1] = n - 1 - u;
        #pragma unroll
        for (int rr = 0; rr < 2; rr++) {
            const int i = rows[rr];
            const float pix = __ldg(&x[3 * i + 0]);
            const float piy = __ldg(&x[3 * i + 1]);
            const float piz = __ldg(&x[3 * i + 2]);
            #pragma unroll 4
            for (int j = i + 1 + tid; j < n; j += TPB) {
                const float dx = __fadd_rn(pix, -__ldg(&x[3 * j + 0]));
                const float dy = __fadd_rn(piy, -__ldg(&x[3 * j + 1]));
                const float dz = __fadd_rn(piz, -__ldg(&x[3 * j + 2]));
                // match jnp exactly: squares, sequential adds, IEEE sqrt
                const float s = __fadd_rn(__fadd_rn(__fmul_rn(dx, dx),
                                                    __fmul_rn(dy, dy)),
                                          __fmul_rn(dz, dz));
                const float d = __fsqrt_rn(s);
                int b = __float2int_ru(__fmul_rn(d, 31.5f));  // == ceil, 1 instr
                b = max(b, 0);
                b = min(b, SBINS - 1);
                // private counter: column = tid -> bank = tid%32, conflict-free
                s_h[(b << 8) + tid] += 1u;
            }
        }
    }
    __syncthreads();

    // Reduce [SBINS][TPB] -> g_hist. 4 threads per bin, rotated columns
    // (conflict-free), then shfl-combine the 4 partials, 1 global RED/bin.
    if (tid < SBINS * 4) {
        const int b = tid >> 2;
        const int q = tid & 3;
        unsigned sum = 0;
        #pragma unroll 8
        for (int c = 0; c < 64; c++) {
            const int col = q * 64 + ((c + tid) & 63);
            sum += s_h[(b << 8) + col];
        }
        sum += __shfl_xor_sync(0xffffffffu, sum, 1);
        sum += __shfl_xor_sync(0xffffffffu, sum, 2);
        if (q == 0 && sum) atomicAdd(&g_hist[b], (int)sum);
    }
}

__global__ void finalize_kernel(float* __restrict__ out, int n) {
    // 64-bin inclusive scan (exact: integer counts < 2^24), then reset g_hist
    // so the next graph replay starts from zero.
    if (threadIdx.x == 0) {
        float acc = 0.0f;
        #pragma unroll
        for (int k = 0; k < NBINS; k++) {
            float v = -(float)g_hist[k];
            if (k == 0) v += (float)n;      // +n vertices at filtration 0
            acc += v;
            out[k] = acc;
            g_hist[k] = 0;
        }
    }
}

extern "C" void kernel_launch(void* const* d_in, const int* in_sizes, int n_in,
                              void* d_out, int out_size) {
    const float* x = (const float*)d_in[0];
    float* out = (float*)d_out;
    const int n = in_sizes[0] / 3;   // 4096

    static_assert(SBINS * TPB * sizeof(unsigned) == 57344, "smem size");
    cudaFuncSetAttribute(hist_kernel,
                         cudaFuncAttributeMaxDynamicSharedMemorySize,
                         SBINS * TPB * (int)sizeof(unsigned));

    hist_kernel<<<GRID, TPB, SBINS * TPB * sizeof(unsigned)>>>(x, n);
    finalize_kernel<<<1, 32>>>(out, n);
}